// round 1
// baseline (speedup 1.0000x reference)
#include <cuda_runtime.h>
#include <math.h>

#define NPTS   (16 * 65536)         // 1,048,576 points (B*N)
#define NMASK  65535
#define NTILES (NPTS / 64)          // 16384
#define EPS    1e-5f

// ---------------- scratch / stats (device globals: no allocation allowed) ----
__device__ __align__(16) float g_y2[(size_t)NPTS * 64];   // y2 pre-BN scratch (268 MB)
__device__ float g_m[3];        // sum X
__device__ float g_S0[6];       // sum X_i X_i^T   (upper tri, 3x3)
__device__ float g_S1[9];       // sum X_i X_{i+1}^T
__device__ float g_S2[9];       // sum X_i X_{i+2}^T
__device__ float g_A1t[12 * 64];// folded layer-1 weight, transposed [k][o]
__device__ float g_C1[64];      // folded layer-1 bias
__device__ float g_sumY[64];    // sum of y2 per channel
__device__ float g_sumY2[64];   // sum of y2^2 per channel
__device__ float g_a2[64];
__device__ float g_c2[64];

// ---------------- 0) zero accumulators (graph replays must reset) ------------
__global__ void k_zero() {
    int t = threadIdx.x;
    if (t < 3)  g_m[t]  = 0.f;
    if (t < 6)  g_S0[t] = 0.f;
    if (t < 9)  { g_S1[t] = 0.f; g_S2[t] = 0.f; }
    if (t < 64) { g_sumY[t] = 0.f; g_sumY2[t] = 0.f; }
}

// ---------------- 1) ring-correlation stats of X ----------------------------
// accumulate mean(3), lag0(6), lag1(9), lag2(9) = 27 sums
__global__ void __launch_bounds__(256) k_stats1(const float* __restrict__ X) {
    float acc[27];
#pragma unroll
    for (int i = 0; i < 27; i++) acc[i] = 0.f;

    int stride = gridDim.x * blockDim.x;
    for (int p = blockIdx.x * blockDim.x + threadIdx.x; p < NPTS; p += stride) {
        int n = p & NMASK;
        const float* xb = X + (size_t)(p - n) * 3;   // batch base
        int n1 = (n + 1) & NMASK;
        int n2 = (n + 2) & NMASK;
        float c0 = xb[3*n+0],  c1 = xb[3*n+1],  c2 = xb[3*n+2];
        float d0 = xb[3*n1+0], d1 = xb[3*n1+1], d2 = xb[3*n1+2];
        float e0 = xb[3*n2+0], e1 = xb[3*n2+1], e2 = xb[3*n2+2];
        acc[0] += c0; acc[1] += c1; acc[2] += c2;
        acc[3] += c0*c0; acc[4] += c0*c1; acc[5] += c0*c2;
        acc[6] += c1*c1; acc[7] += c1*c2; acc[8] += c2*c2;
        acc[ 9] += c0*d0; acc[10] += c0*d1; acc[11] += c0*d2;
        acc[12] += c1*d0; acc[13] += c1*d1; acc[14] += c1*d2;
        acc[15] += c2*d0; acc[16] += c2*d1; acc[17] += c2*d2;
        acc[18] += c0*e0; acc[19] += c0*e1; acc[20] += c0*e2;
        acc[21] += c1*e0; acc[22] += c1*e1; acc[23] += c1*e2;
        acc[24] += c2*e0; acc[25] += c2*e1; acc[26] += c2*e2;
    }
    // warp tree-reduce
#pragma unroll
    for (int i = 0; i < 27; i++) {
#pragma unroll
        for (int off = 16; off > 0; off >>= 1)
            acc[i] += __shfl_down_sync(0xffffffffu, acc[i], off);
    }
    if ((threadIdx.x & 31) == 0) {
#pragma unroll
        for (int i = 0; i < 3; i++) atomicAdd(&g_m[i],  acc[i]);
#pragma unroll
        for (int i = 0; i < 6; i++) atomicAdd(&g_S0[i], acc[3 + i]);
#pragma unroll
        for (int i = 0; i < 9; i++) atomicAdd(&g_S1[i], acc[9 + i]);
#pragma unroll
        for (int i = 0; i < 9; i++) atomicAdd(&g_S2[i], acc[18 + i]);
    }
}

// ---------------- 2) analytic BN1 fold ---------------------------------------
// h = [Xc, Xc-Xp, Xc-Xn, Xn-Xp]; y1 = W1 h + b1.
// For w = W1[o,:]:  u_p = -w[3:6]-w[9:12], u_c = w[0:3]+w[3:6]+w[6:9], u_n = -w[6:9]+w[9:12]
// mean = (u_p+u_c+u_n)·m + b1 ; var = u^T M9 u - (u·E[s])^2 from lag moments.
__global__ void k_fin1(const float* __restrict__ W1, const float* __restrict__ b1,
                       const float* __restrict__ g1, const float* __restrict__ beta1) {
    int o = threadIdx.x;
    if (o >= 64) return;
    const float inv = 1.0f / (float)NPTS;

    float m[3];
    for (int f = 0; f < 3; f++) m[f] = g_m[f] * inv;
    float S0f[3][3], S1f[3][3], S2f[3][3];
    // expand symmetric lag-0
    S0f[0][0] = g_S0[0]*inv; S0f[0][1] = g_S0[1]*inv; S0f[0][2] = g_S0[2]*inv;
    S0f[1][0] = S0f[0][1];   S0f[1][1] = g_S0[3]*inv; S0f[1][2] = g_S0[4]*inv;
    S0f[2][0] = S0f[0][2];   S0f[2][1] = S0f[1][2];   S0f[2][2] = g_S0[5]*inv;
    for (int f = 0; f < 3; f++)
        for (int g = 0; g < 3; g++) {
            S1f[f][g] = g_S1[f*3+g] * inv;
            S2f[f][g] = g_S2[f*3+g] * inv;
        }

    float w[12];
    for (int k = 0; k < 12; k++) w[k] = W1[o*12 + k];
    float up[3], uc[3], un[3];
    for (int f = 0; f < 3; f++) {
        up[f] = -w[3+f] - w[9+f];
        uc[f] =  w[f] + w[3+f] + w[6+f];
        un[f] = -w[6+f] + w[9+f];
    }
    float meanlin = 0.f;
    for (int f = 0; f < 3; f++) meanlin += (up[f] + uc[f] + un[f]) * m[f];

    float q = 0.f;
    for (int f = 0; f < 3; f++)
        for (int g = 0; g < 3; g++) {
            q += (up[f]*up[g] + uc[f]*uc[g] + un[f]*un[g]) * S0f[f][g];
            q += 2.0f * (up[f]*uc[g] + uc[f]*un[g]) * S1f[f][g];
            q += 2.0f * (up[f]*un[g]) * S2f[f][g];
        }
    float var = q - meanlin * meanlin;
    float a = g1[o] * rsqrtf(var + EPS);
    g_C1[o] = beta1[o] - a * meanlin;
    for (int k = 0; k < 12; k++) g_A1t[k*64 + o] = a * w[k];
}

// ---------------- 3) main fused pass -----------------------------------------
// per 64-point tile: h -> z1 (GEMM1 + folded BN1 + relu) -> y2 (GEMM2),
// write y2 scratch, accumulate per-channel sum/sumsq.
__global__ void __launch_bounds__(256) k_main(const float* __restrict__ X,
                                              const float* __restrict__ W2,
                                              const float* __restrict__ b2) {
    __shared__ float hsh[12][68];     // [feat][pt], padded
    __shared__ float zsh[64][68];     // [k=layer1 ch][pt], padded
    __shared__ float w2sh[64 * 64];   // [k][o]  (W2 transposed)
    __shared__ float a1sh[12 * 64];   // [k][o]
    __shared__ float c1sh[64];
    __shared__ float b2sh[64];
    __shared__ float red[16][64];

    int tid = threadIdx.x;
    int tx = tid & 15;    // channel group: ch = tx*4 + i
    int ty = tid >> 4;    // point  group: pt = ty*4 + j

    for (int i = tid; i < 64 * 64; i += 256) {
        int k = i >> 6, o = i & 63;
        w2sh[i] = W2[o * 64 + k];           // transpose into [k][o]
    }
    for (int i = tid; i < 12 * 64; i += 256) a1sh[i] = g_A1t[i];
    if (tid < 64) { c1sh[tid] = g_C1[tid]; b2sh[tid] = b2[tid]; }

    float ssum[4] = {0.f, 0.f, 0.f, 0.f};
    float ssq[4]  = {0.f, 0.f, 0.f, 0.f};

    for (int tile = blockIdx.x; tile < NTILES; tile += gridDim.x) {
        __syncthreads();   // also covers initial weight-load barrier
        if (tid < 64) {
            int p = tile * 64 + tid;
            int n = p & NMASK;
            const float* xb = X + (size_t)(p - n) * 3;
            int np = (n + NMASK) & NMASK;
            int nn = (n + 1) & NMASK;
            float c0 = xb[3*n+0],  c1 = xb[3*n+1],  c2 = xb[3*n+2];
            float p0 = xb[3*np+0], p1 = xb[3*np+1], p2 = xb[3*np+2];
            float q0 = xb[3*nn+0], q1 = xb[3*nn+1], q2 = xb[3*nn+2];
            hsh[0][tid] = c0;       hsh[1][tid]  = c1;       hsh[2][tid]  = c2;
            hsh[3][tid] = c0 - p0;  hsh[4][tid]  = c1 - p1;  hsh[5][tid]  = c2 - p2;
            hsh[6][tid] = c0 - q0;  hsh[7][tid]  = c1 - q1;  hsh[8][tid]  = c2 - q2;
            hsh[9][tid] = q0 - p0;  hsh[10][tid] = q1 - p1;  hsh[11][tid] = q2 - p2;
        }
        __syncthreads();

        // ---- GEMM1: z[ch][pt] = relu(C1[ch] + sum_k A1t[k][ch] * h[k][pt])
        float acc[4][4];
#pragma unroll
        for (int i = 0; i < 4; i++) {
            float ci = c1sh[tx*4 + i];
#pragma unroll
            for (int j = 0; j < 4; j++) acc[i][j] = ci;
        }
#pragma unroll
        for (int k = 0; k < 12; k++) {
            float4 wv = *(const float4*)&a1sh[k*64 + tx*4];
            float4 hv = *(const float4*)&hsh[k][ty*4];
            float wr[4] = {wv.x, wv.y, wv.z, wv.w};
            float hr[4] = {hv.x, hv.y, hv.z, hv.w};
#pragma unroll
            for (int i = 0; i < 4; i++)
#pragma unroll
                for (int j = 0; j < 4; j++)
                    acc[i][j] = fmaf(wr[i], hr[j], acc[i][j]);
        }
#pragma unroll
        for (int i = 0; i < 4; i++) {
            float4 z4;
            z4.x = fmaxf(acc[i][0], 0.f);
            z4.y = fmaxf(acc[i][1], 0.f);
            z4.z = fmaxf(acc[i][2], 0.f);
            z4.w = fmaxf(acc[i][3], 0.f);
            *(float4*)&zsh[tx*4 + i][ty*4] = z4;
        }
        __syncthreads();

        // ---- GEMM2: y[ch][pt] = b2[ch] + sum_k W2t[k][ch] * z[k][pt]
        float d[4][4];
#pragma unroll
        for (int i = 0; i < 4; i++) {
            float bi = b2sh[tx*4 + i];
#pragma unroll
            for (int j = 0; j < 4; j++) d[i][j] = bi;
        }
#pragma unroll
        for (int k = 0; k < 64; k++) {
            float4 wv = *(const float4*)&w2sh[k*64 + tx*4];
            float4 zv = *(const float4*)&zsh[k][ty*4];
            float wr[4] = {wv.x, wv.y, wv.z, wv.w};
            float zr[4] = {zv.x, zv.y, zv.z, zv.w};
#pragma unroll
            for (int i = 0; i < 4; i++)
#pragma unroll
                for (int j = 0; j < 4; j++)
                    d[i][j] = fmaf(wr[i], zr[j], d[i][j]);
        }

        // ---- write y2 scratch (coalesced float4) + local stats
        size_t rowbase = (size_t)tile * 64 + (size_t)(ty * 4);
#pragma unroll
        for (int j = 0; j < 4; j++) {
            float4 o4 = make_float4(d[0][j], d[1][j], d[2][j], d[3][j]);
            *(float4*)&g_y2[(rowbase + j) * 64 + tx*4] = o4;
#pragma unroll
            for (int i = 0; i < 4; i++) {
                ssum[i] += d[i][j];
                ssq[i]  += d[i][j] * d[i][j];
            }
        }
    }

    // ---- block-level stat reduction, one atomic pair per channel per block
    __syncthreads();
#pragma unroll
    for (int i = 0; i < 4; i++) red[ty][tx*4 + i] = ssum[i];
    __syncthreads();
    if (tid < 64) {
        float t = 0.f;
#pragma unroll
        for (int y = 0; y < 16; y++) t += red[y][tid];
        atomicAdd(&g_sumY[tid], t);
    }
    __syncthreads();
#pragma unroll
    for (int i = 0; i < 4; i++) red[ty][tx*4 + i] = ssq[i];
    __syncthreads();
    if (tid < 64) {
        float t = 0.f;
#pragma unroll
        for (int y = 0; y < 16; y++) t += red[y][tid];
        atomicAdd(&g_sumY2[tid], t);
    }
}

// ---------------- 4) finalize BN2 constants ----------------------------------
__global__ void k_fin2(const float* __restrict__ g2, const float* __restrict__ beta2) {
    int o = threadIdx.x;
    if (o >= 64) return;
    const float inv = 1.0f / (float)NPTS;
    float mean = g_sumY[o] * inv;
    float var  = g_sumY2[o] * inv - mean * mean;
    float a = g2[o] * rsqrtf(var + EPS);
    g_a2[o] = a;
    g_c2[o] = beta2[o] - a * mean;
}

// ---------------- 5) apply BN2 + relu, write output (memory-bound) -----------
__global__ void __launch_bounds__(256) k_out(float* __restrict__ out) {
    __shared__ float a2s[64], c2s[64];
    if (threadIdx.x < 64) {
        a2s[threadIdx.x] = g_a2[threadIdx.x];
        c2s[threadIdx.x] = g_c2[threadIdx.x];
    }
    __syncthreads();
    const float4* in4 = (const float4*)g_y2;
    float4* out4 = (float4*)out;
    const int total4 = NPTS * 64 / 4;   // 16,777,216
    int stride = gridDim.x * blockDim.x;
    for (int i = blockIdx.x * blockDim.x + threadIdx.x; i < total4; i += stride) {
        float4 v = in4[i];
        int ch = (i & 15) * 4;
        v.x = fmaxf(fmaf(v.x, a2s[ch + 0], c2s[ch + 0]), 0.f);
        v.y = fmaxf(fmaf(v.y, a2s[ch + 1], c2s[ch + 1]), 0.f);
        v.z = fmaxf(fmaf(v.z, a2s[ch + 2], c2s[ch + 2]), 0.f);
        v.w = fmaxf(fmaf(v.w, a2s[ch + 3], c2s[ch + 3]), 0.f);
        out4[i] = v;
    }
}

// ---------------- launch ------------------------------------------------------
extern "C" void kernel_launch(void* const* d_in, const int* in_sizes, int n_in,
                              void* d_out, int out_size) {
    const float* X     = (const float*)d_in[0];
    const float* W1    = (const float*)d_in[1];
    const float* b1    = (const float*)d_in[2];
    const float* g1    = (const float*)d_in[3];
    const float* beta1 = (const float*)d_in[4];
    const float* W2    = (const float*)d_in[5];
    const float* b2    = (const float*)d_in[6];
    const float* g2    = (const float*)d_in[7];
    const float* beta2 = (const float*)d_in[8];
    float* out = (float*)d_out;
    (void)in_sizes; (void)n_in; (void)out_size;

    k_zero<<<1, 256>>>();
    k_stats1<<<1024, 256>>>(X);
    k_fin1<<<1, 64>>>(W1, b1, g1, beta1);
    k_main<<<2048, 256>>>(X, W2, b2);
    k_fin2<<<1, 64>>>(g2, beta2);
    k_out<<<2048, 256>>>(out);
}

// round 2
// speedup vs baseline: 1.0760x; 1.0760x over previous
#include <cuda_runtime.h>
#include <math.h>

#define NPTS    (16 * 65536)        // 1,048,576 points (B*N)
#define NMASK   65535
#define TILE    256
#define NTILES2 (NPTS / TILE)       // 4096
#define EPS     1e-5f

// ---------------- scratch / stats (device globals: no allocation allowed) ----
__device__ __align__(16) float g_y2[(size_t)NPTS * 64];   // y2 pre-BN scratch (268 MB)
__device__ float g_m[3];
__device__ float g_S0[6];
__device__ float g_S1[9];
__device__ float g_S2[9];
__device__ float g_A1t[12 * 64];    // folded layer-1 weight, transposed [k][o]
__device__ float g_C1[64];
__device__ float g_sumY[64];
__device__ float g_sumY2[64];
__device__ float g_a2[64];
__device__ float g_c2[64];

// ---------------- 0) zero accumulators ---------------------------------------
__global__ void k_zero() {
    int t = threadIdx.x;
    if (t < 3)  g_m[t]  = 0.f;
    if (t < 6)  g_S0[t] = 0.f;
    if (t < 9)  { g_S1[t] = 0.f; g_S2[t] = 0.f; }
    if (t < 64) { g_sumY[t] = 0.f; g_sumY2[t] = 0.f; }
}

// ---------------- 1) ring-correlation stats of X -----------------------------
__global__ void __launch_bounds__(256) k_stats1(const float* __restrict__ X) {
    float acc[27];
#pragma unroll
    for (int i = 0; i < 27; i++) acc[i] = 0.f;

    int stride = gridDim.x * blockDim.x;
    for (int p = blockIdx.x * blockDim.x + threadIdx.x; p < NPTS; p += stride) {
        int n = p & NMASK;
        const float* xb = X + (size_t)(p - n) * 3;
        int n1 = (n + 1) & NMASK;
        int n2 = (n + 2) & NMASK;
        float c0 = xb[3*n+0],  c1 = xb[3*n+1],  c2 = xb[3*n+2];
        float d0 = xb[3*n1+0], d1 = xb[3*n1+1], d2 = xb[3*n1+2];
        float e0 = xb[3*n2+0], e1 = xb[3*n2+1], e2 = xb[3*n2+2];
        acc[0] += c0; acc[1] += c1; acc[2] += c2;
        acc[3] += c0*c0; acc[4] += c0*c1; acc[5] += c0*c2;
        acc[6] += c1*c1; acc[7] += c1*c2; acc[8] += c2*c2;
        acc[ 9] += c0*d0; acc[10] += c0*d1; acc[11] += c0*d2;
        acc[12] += c1*d0; acc[13] += c1*d1; acc[14] += c1*d2;
        acc[15] += c2*d0; acc[16] += c2*d1; acc[17] += c2*d2;
        acc[18] += c0*e0; acc[19] += c0*e1; acc[20] += c0*e2;
        acc[21] += c1*e0; acc[22] += c1*e1; acc[23] += c1*e2;
        acc[24] += c2*e0; acc[25] += c2*e1; acc[26] += c2*e2;
    }
#pragma unroll
    for (int i = 0; i < 27; i++) {
#pragma unroll
        for (int off = 16; off > 0; off >>= 1)
            acc[i] += __shfl_down_sync(0xffffffffu, acc[i], off);
    }
    if ((threadIdx.x & 31) == 0) {
#pragma unroll
        for (int i = 0; i < 3; i++) atomicAdd(&g_m[i],  acc[i]);
#pragma unroll
        for (int i = 0; i < 6; i++) atomicAdd(&g_S0[i], acc[3 + i]);
#pragma unroll
        for (int i = 0; i < 9; i++) atomicAdd(&g_S1[i], acc[9 + i]);
#pragma unroll
        for (int i = 0; i < 9; i++) atomicAdd(&g_S2[i], acc[18 + i]);
    }
}

// ---------------- 2) analytic BN1 fold ----------------------------------------
__global__ void k_fin1(const float* __restrict__ W1, const float* __restrict__ b1,
                       const float* __restrict__ g1, const float* __restrict__ beta1) {
    int o = threadIdx.x;
    if (o >= 64) return;
    const float inv = 1.0f / (float)NPTS;

    float m[3];
    for (int f = 0; f < 3; f++) m[f] = g_m[f] * inv;
    float S0f[3][3], S1f[3][3], S2f[3][3];
    S0f[0][0] = g_S0[0]*inv; S0f[0][1] = g_S0[1]*inv; S0f[0][2] = g_S0[2]*inv;
    S0f[1][0] = S0f[0][1];   S0f[1][1] = g_S0[3]*inv; S0f[1][2] = g_S0[4]*inv;
    S0f[2][0] = S0f[0][2];   S0f[2][1] = S0f[1][2];   S0f[2][2] = g_S0[5]*inv;
    for (int f = 0; f < 3; f++)
        for (int g = 0; g < 3; g++) {
            S1f[f][g] = g_S1[f*3+g] * inv;
            S2f[f][g] = g_S2[f*3+g] * inv;
        }

    float w[12];
    for (int k = 0; k < 12; k++) w[k] = W1[o*12 + k];
    float up[3], uc[3], un[3];
    for (int f = 0; f < 3; f++) {
        up[f] = -w[3+f] - w[9+f];
        uc[f] =  w[f] + w[3+f] + w[6+f];
        un[f] = -w[6+f] + w[9+f];
    }
    float meanlin = 0.f;
    for (int f = 0; f < 3; f++) meanlin += (up[f] + uc[f] + un[f]) * m[f];

    float q = 0.f;
    for (int f = 0; f < 3; f++)
        for (int g = 0; g < 3; g++) {
            q += (up[f]*up[g] + uc[f]*uc[g] + un[f]*un[g]) * S0f[f][g];
            q += 2.0f * (up[f]*uc[g] + uc[f]*un[g]) * S1f[f][g];
            q += 2.0f * (up[f]*un[g]) * S2f[f][g];
        }
    float var = q - meanlin * meanlin;
    float a = g1[o] * rsqrtf(var + EPS);
    g_C1[o] = beta1[o] - a * meanlin;
    for (int k = 0; k < 12; k++) g_A1t[k*64 + o] = a * w[k];
}

// ---------------- 3) main fused pass: 256-pt tiles, 8x8 microkernel -----------
// Shared carve (floats):
//   Z  [64][256]   swizzled: phys col = col ^ (((row>>3)&7)<<2)
//   Wt [64][68]    phys col = o + ((o>>5)<<2)   (conflict-free quads)
//   A1 [12][68]    same layout
//   H  [12][264]
//   C1 [64], B2 [64]
#define Z_OFF  0
#define W_OFF  (64*256)
#define A_OFF  (W_OFF + 64*68)
#define H_OFF  (A_OFF + 12*68)
#define C_OFF  (H_OFF + 12*264)
#define B_OFF  (C_OFF + 64)
#define SMEM_FLOATS (B_OFF + 64)
#define SMEM_BYTES  (SMEM_FLOATS * 4)

__global__ void __launch_bounds__(256, 2) k_main(const float* __restrict__ X,
                                                 const float* __restrict__ W2,
                                                 const float* __restrict__ b2) {
    extern __shared__ float sm[];
    float* Z  = sm + Z_OFF;
    float* Wt = sm + W_OFF;
    float* A1 = sm + A_OFF;
    float* H  = sm + H_OFF;
    float* C1 = sm + C_OFF;
    float* B2 = sm + B_OFF;

    int tid = threadIdx.x;
    int tx = tid & 7;          // channel group: ch = tx*8 + i
    int ty = tid >> 3;         // point group:   pt = ty*8 + j
    int woff = tx*8 + ((tx >> 2) << 2);   // conflict-free W/A column

    // stage weights once per block
    for (int i = tid; i < 64*64; i += 256) {
        int o = i >> 6, k = i & 63;        // W2 read coalesced: W2[o][k]
        Wt[k*68 + o + ((o >> 5) << 2)] = W2[i];
    }
    for (int i = tid; i < 12*64; i += 256) {
        int k = i >> 6, o = i & 63;
        A1[k*68 + o + ((o >> 5) << 2)] = g_A1t[i];
    }
    if (tid < 64) { C1[tid] = g_C1[tid]; B2[tid] = b2[tid]; }

    float ssum[8], ssq[8];
#pragma unroll
    for (int i = 0; i < 8; i++) { ssum[i] = 0.f; ssq[i] = 0.f; }

    for (int tile = blockIdx.x; tile < NTILES2; tile += gridDim.x) {
        __syncthreads();   // prev GEMM2 done reading Z; weights ready on iter 0
        {
            int p = tile * TILE + tid;
            int n = p & NMASK;
            const float* xb = X + (size_t)(p - n) * 3;
            int np = (n + NMASK) & NMASK;
            int nn = (n + 1) & NMASK;
            float c0 = xb[3*n+0],  c1 = xb[3*n+1],  c2 = xb[3*n+2];
            float p0 = xb[3*np+0], p1 = xb[3*np+1], p2 = xb[3*np+2];
            float q0 = xb[3*nn+0], q1 = xb[3*nn+1], q2 = xb[3*nn+2];
            H[0*264+tid] = c0;      H[1*264+tid]  = c1;      H[2*264+tid]  = c2;
            H[3*264+tid] = c0-p0;   H[4*264+tid]  = c1-p1;   H[5*264+tid]  = c2-p2;
            H[6*264+tid] = c0-q0;   H[7*264+tid]  = c1-q1;   H[8*264+tid]  = c2-q2;
            H[9*264+tid] = q0-p0;   H[10*264+tid] = q1-p1;   H[11*264+tid] = q2-p2;
        }
        __syncthreads();

        // ---- GEMM1: z[ch][pt] = relu(C1 + sum_k A1[k][ch]*H[k][pt]), K=12
        float acc[8][8];
#pragma unroll
        for (int i = 0; i < 8; i++) {
            float ci = C1[tx*8 + i];
#pragma unroll
            for (int j = 0; j < 8; j++) acc[i][j] = ci;
        }
#pragma unroll
        for (int k = 0; k < 12; k++) {
            float4 wa = *(const float4*)&A1[k*68 + woff];
            float4 wb = *(const float4*)&A1[k*68 + woff + 4];
            float4 ha = *(const float4*)&H[k*264 + ty*8];
            float4 hb = *(const float4*)&H[k*264 + ty*8 + 4];
            float wr[8] = {wa.x, wa.y, wa.z, wa.w, wb.x, wb.y, wb.z, wb.w};
            float hr[8] = {ha.x, ha.y, ha.z, ha.w, hb.x, hb.y, hb.z, hb.w};
#pragma unroll
            for (int i = 0; i < 8; i++)
#pragma unroll
                for (int j = 0; j < 8; j++)
                    acc[i][j] = fmaf(wr[i], hr[j], acc[i][j]);
        }
        // relu + swizzled store to Z
        {
            int s = tx << 2;
            int c0p = (ty*8) ^ s;
#pragma unroll
            for (int i = 0; i < 8; i++) {
                int r = tx*8 + i;
                float4 za, zb;
                za.x = fmaxf(acc[i][0], 0.f); za.y = fmaxf(acc[i][1], 0.f);
                za.z = fmaxf(acc[i][2], 0.f); za.w = fmaxf(acc[i][3], 0.f);
                zb.x = fmaxf(acc[i][4], 0.f); zb.y = fmaxf(acc[i][5], 0.f);
                zb.z = fmaxf(acc[i][6], 0.f); zb.w = fmaxf(acc[i][7], 0.f);
                *(float4*)&Z[r*256 + c0p]       = za;
                *(float4*)&Z[r*256 + (c0p ^ 4)] = zb;
            }
        }
        __syncthreads();

        // ---- GEMM2: y[ch][pt] = B2 + sum_k Wt[k][ch]*Z[k][pt], K=64
        float d[8][8];
#pragma unroll
        for (int i = 0; i < 8; i++) {
            float bi = B2[tx*8 + i];
#pragma unroll
            for (int j = 0; j < 8; j++) d[i][j] = bi;
        }
#pragma unroll 8
        for (int k = 0; k < 64; k++) {
            int sk = ((k >> 3) & 7) << 2;
            float4 wa = *(const float4*)&Wt[k*68 + woff];
            float4 wb = *(const float4*)&Wt[k*68 + woff + 4];
            int zc = (ty*8) ^ sk;
            float4 za = *(const float4*)&Z[k*256 + zc];
            float4 zb = *(const float4*)&Z[k*256 + (zc ^ 4)];
            float wr[8] = {wa.x, wa.y, wa.z, wa.w, wb.x, wb.y, wb.z, wb.w};
            float zr[8] = {za.x, za.y, za.z, za.w, zb.x, zb.y, zb.z, zb.w};
#pragma unroll
            for (int i = 0; i < 8; i++)
#pragma unroll
                for (int j = 0; j < 8; j++)
                    d[i][j] = fmaf(wr[i], zr[j], d[i][j]);
        }

        // ---- store y2 + local stats
        size_t ptbase = (size_t)tile * TILE + (size_t)(ty * 8);
#pragma unroll
        for (int j = 0; j < 8; j++) {
            float4 oa = make_float4(d[0][j], d[1][j], d[2][j], d[3][j]);
            float4 ob = make_float4(d[4][j], d[5][j], d[6][j], d[7][j]);
            float* row = &g_y2[(ptbase + j) * 64 + tx*8];
            *(float4*)row       = oa;
            *(float4*)(row + 4) = ob;
#pragma unroll
            for (int i = 0; i < 8; i++) {
                ssum[i] += d[i][j];
                ssq[i]  += d[i][j] * d[i][j];
            }
        }
    }

    // ---- stats reduction: warp shuffle (ty within warp), then smem, then atomics
    __syncthreads();
    float* R1 = H;            // reuse H region: 8 warps x 64 ch
    float* R2 = H + 512;
    int lane = tid & 31, warp = tid >> 5;
#pragma unroll
    for (int i = 0; i < 8; i++) {
        float a = ssum[i], b = ssq[i];
        a += __shfl_down_sync(0xffffffffu, a, 16);
        a += __shfl_down_sync(0xffffffffu, a, 8);
        b += __shfl_down_sync(0xffffffffu, b, 16);
        b += __shfl_down_sync(0xffffffffu, b, 8);
        if (lane < 8) {
            R1[warp*64 + lane*8 + i] = a;
            R2[warp*64 + lane*8 + i] = b;
        }
    }
    __syncthreads();
    if (tid < 64) {
        float t1 = 0.f, t2 = 0.f;
#pragma unroll
        for (int w = 0; w < 8; w++) { t1 += R1[w*64 + tid]; t2 += R2[w*64 + tid]; }
        atomicAdd(&g_sumY[tid], t1);
        atomicAdd(&g_sumY2[tid], t2);
    }
}

// ---------------- 4) finalize BN2 constants ------------------------------------
__global__ void k_fin2(const float* __restrict__ g2, const float* __restrict__ beta2) {
    int o = threadIdx.x;
    if (o >= 64) return;
    const float inv = 1.0f / (float)NPTS;
    float mean = g_sumY[o] * inv;
    float var  = g_sumY2[o] * inv - mean * mean;
    float a = g2[o] * rsqrtf(var + EPS);
    g_a2[o] = a;
    g_c2[o] = beta2[o] - a * mean;
}

// ---------------- 5) apply BN2 + relu, write output ----------------------------
// grid MUST be 4096 x 256: total4 = 16 * stride exactly (no bounds checks).
__global__ void __launch_bounds__(256) k_out(float* __restrict__ out) {
    __shared__ float a2s[64], c2s[64];
    if (threadIdx.x < 64) {
        a2s[threadIdx.x] = g_a2[threadIdx.x];
        c2s[threadIdx.x] = g_c2[threadIdx.x];
    }
    __syncthreads();
    const float4* in4 = (const float4*)g_y2;
    float4* out4 = (float4*)out;
    const int stride = 4096 * 256;           // gridDim.x * blockDim.x
    int i = blockIdx.x * blockDim.x + threadIdx.x;
    int ch = (i & 15) * 4;                   // stride % 16 == 0 -> fixed per thread
    float a0 = a2s[ch+0], a1 = a2s[ch+1], a2 = a2s[ch+2], a3 = a2s[ch+3];
    float c0 = c2s[ch+0], c1 = c2s[ch+1], c2 = c2s[ch+2], c3 = c2s[ch+3];
#pragma unroll
    for (int it = 0; it < 4; it++) {
        float4 v0 = in4[i];
        float4 v1 = in4[i +     stride];
        float4 v2 = in4[i + 2 * stride];
        float4 v3 = in4[i + 3 * stride];
        v0.x = fmaxf(fmaf(v0.x, a0, c0), 0.f); v0.y = fmaxf(fmaf(v0.y, a1, c1), 0.f);
        v0.z = fmaxf(fmaf(v0.z, a2, c2), 0.f); v0.w = fmaxf(fmaf(v0.w, a3, c3), 0.f);
        v1.x = fmaxf(fmaf(v1.x, a0, c0), 0.f); v1.y = fmaxf(fmaf(v1.y, a1, c1), 0.f);
        v1.z = fmaxf(fmaf(v1.z, a2, c2), 0.f); v1.w = fmaxf(fmaf(v1.w, a3, c3), 0.f);
        v2.x = fmaxf(fmaf(v2.x, a0, c0), 0.f); v2.y = fmaxf(fmaf(v2.y, a1, c1), 0.f);
        v2.z = fmaxf(fmaf(v2.z, a2, c2), 0.f); v2.w = fmaxf(fmaf(v2.w, a3, c3), 0.f);
        v3.x = fmaxf(fmaf(v3.x, a0, c0), 0.f); v3.y = fmaxf(fmaf(v3.y, a1, c1), 0.f);
        v3.z = fmaxf(fmaf(v3.z, a2, c2), 0.f); v3.w = fmaxf(fmaf(v3.w, a3, c3), 0.f);
        out4[i]              = v0;
        out4[i +     stride] = v1;
        out4[i + 2 * stride] = v2;
        out4[i + 3 * stride] = v3;
        i += 4 * stride;
    }
}

// ---------------- launch --------------------------------------------------------
extern "C" void kernel_launch(void* const* d_in, const int* in_sizes, int n_in,
                              void* d_out, int out_size) {
    const float* X     = (const float*)d_in[0];
    const float* W1    = (const float*)d_in[1];
    const float* b1    = (const float*)d_in[2];
    const float* g1    = (const float*)d_in[3];
    const float* beta1 = (const float*)d_in[4];
    const float* W2    = (const float*)d_in[5];
    const float* b2    = (const float*)d_in[6];
    const float* g2    = (const float*)d_in[7];
    const float* beta2 = (const float*)d_in[8];
    float* out = (float*)d_out;
    (void)in_sizes; (void)n_in; (void)out_size;

    cudaFuncSetAttribute((const void*)k_main,
                         cudaFuncAttributeMaxDynamicSharedMemorySize, SMEM_BYTES);

    k_zero<<<1, 256>>>();
    k_stats1<<<1024, 256>>>(X);
    k_fin1<<<1, 64>>>(W1, b1, g1, beta1);
    k_main<<<296, 256, SMEM_BYTES>>>(X, W2, b2);
    k_fin2<<<1, 64>>>(g2, beta2);
    k_out<<<4096, 256>>>(out);
}